// round 7
// baseline (speedup 1.0000x reference)
#include <cuda_runtime.h>
#include <cuda_fp16.h>

// ---------------------------------------------------------------------------
// UNetV2 on GB300: gather-GEMM-scatter subm conv, center tap fused into the
// epilogue ("PREV" form), acc buffers memset + bot-half nb conv forked onto
// side streams so they overlap the serial conv chain.
// Each acc slice has a PAD ROW at index n (scatter sentinel target).
// ---------------------------------------------------------------------------

#define MAXN 500000
#define NC   32
#define SEG  16384
#define NBK  26
#define BLKSEG 64
#define ASTRIDE ((size_t)(MAXN + 1) * NC)   // acc slice stride incl. pad row

static __device__ float  g_acc[4 * ASTRIDE];
static __device__ __half g_h1[MAXN * NC];
static __device__ __half g_h2[MAXN * NC];
static __device__ __half g_h3[MAXN * NC];
static __device__ int2   g_rb[NBK * SEG];
static __device__ int    g_kcnt[32];

typedef unsigned long long u64;

__device__ __forceinline__ u64 splat2(float a) {
    u64 r; asm("mov.b64 %0, {%1, %1};" : "=l"(r) : "f"(a)); return r;
}
__device__ __forceinline__ u64 pack2(float a, float b) {
    u64 r; asm("mov.b64 %0, {%1, %2};" : "=l"(r) : "f"(a), "f"(b)); return r;
}
__device__ __forceinline__ void fma2(u64& d, u64 a, u64 b) {
    asm("fma.rn.f32x2 %0, %1, %2, %3;" : "=l"(d) : "l"(a), "l"(b), "l"(d));
}
__device__ __forceinline__ float2 unpack2(u64 a) {
    float2 r; asm("mov.b64 {%0, %1}, %2;" : "=f"(r.x), "=f"(r.y) : "l"(a)); return r;
}
__device__ __forceinline__ void redadd(float* p, float v) {
    asm volatile("red.global.add.f32 [%0], %1;" :: "l"(p), "f"(v) : "memory");
}
__device__ __forceinline__ float loadf(const float* p)  { return __ldg(p); }
__device__ __forceinline__ float loadf(const __half* p) { return __half2float(__ldg(p)); }
__device__ __forceinline__ void storef(float* p, float v)  { *p = v; }
__device__ __forceinline__ void storef(__half* p, float v) { *p = __float2half(v); }

// ---------------------------------------------------------------------------
__global__ __launch_bounds__(256)
void build_rb(const int* __restrict__ nbr, int n)
{
    __shared__ int nsh[256 * 27];
    const int tid  = threadIdx.x;
    const int lane = tid & 31;
    const long long base = (long long)blockIdx.x * 256;

    for (int i = tid; i < 256 * 27; i += 256) {
        long long g = base * 27 + i;
        nsh[i] = (g < (long long)n * 27) ? nbr[g] : n;
    }
    __syncthreads();

    const int v = (int)(base + tid);
    const bool live = v < n;

    #pragma unroll 1
    for (int j = 0; j < NBK; ++j) {
        int k = (j < 13) ? j : j + 1;
        int u = nsh[tid * 27 + k];
        bool want = live && ((unsigned)u < (unsigned)n);
        unsigned m = __ballot_sync(0xffffffffu, want);
        int rank = __popc(m & ((1u << lane) - 1));
        int leader = (m != 0u) ? (__ffs(m) - 1) : 0;
        int bp = 0;
        if (m != 0u && lane == leader) bp = atomicAdd(&g_kcnt[j], __popc(m));
        bp = __shfl_sync(0xffffffffu, bp, leader);
        int pos = bp + rank;
        if (want && pos < SEG) g_rb[j * SEG + pos] = make_int2(v, u);
    }
}

// ---------------------------------------------------------------------------
__device__ __forceinline__ void pair_gemm(const u64* f, const u64* wsp, int p,
                                          float& rA, float& rB)
{
    const ulonglong2* row = (const ulonglong2*)(f + p * 32);
    u64 aE = 0ull, aO = 0ull;
    #pragma unroll
    for (int c2 = 0; c2 < 16; ++c2) {
        ulonglong2 q = row[c2];
        fma2(aE, q.x, wsp[2 * c2]);
        fma2(aO, q.y, wsp[2 * c2 + 1]);
    }
    float2 e = unpack2(aE), o = unpack2(aO);
    rA = e.x + o.x;
    rB = e.y + o.y;
}

// ---------------------------------------------------------------------------
// neighbor taps: acc[v] += Wk^T x[u]; sentinel entries (v==n) hit the pad row
// ---------------------------------------------------------------------------
template <typename T>
__global__ __launch_bounds__(256)
void nb_conv(const T* __restrict__ x, const float* __restrict__ W,
             int kstride, int hoff, float* __restrict__ acc, int n)
{
    __shared__ u64 ft[8 * 512];
    const int j   = blockIdx.x / BLKSEG;
    const int bis = blockIdx.x % BLKSEG;
    const int cnt = g_kcnt[j];
    if (bis * 256 >= cnt) return;

    const int k = (j < 13) ? j : j + 1;
    const float* Wk = W + (size_t)k * kstride + hoff;

    const int lane = threadIdx.x & 31;
    const int warp = threadIdx.x >> 5;

    u64 wsp[32];
    #pragma unroll
    for (int c = 0; c < 32; ++c) wsp[c] = splat2(__ldg(Wk + c * 32 + lane));

    const int eidx = bis * 256 + warp * 32 + lane;
    int2 e = (eidx < cnt) ? __ldg(&g_rb[j * SEG + eidx]) : make_int2(n, 0);

    u64* f = ft + warp * 512;
    #pragma unroll 4
    for (int p = 0; p < 16; ++p) {
        int uA = __shfl_sync(0xffffffffu, e.y, 2 * p);
        int uB = __shfl_sync(0xffffffffu, e.y, 2 * p + 1);
        f[p * 32 + lane] = pack2(loadf(x + (size_t)uA * 32 + lane),
                                 loadf(x + (size_t)uB * 32 + lane));
    }
    __syncwarp();

    #pragma unroll 2
    for (int p = 0; p < 16; ++p) {
        float rA, rB;
        pair_gemm(f, wsp, p, rA, rB);
        int vA = __shfl_sync(0xffffffffu, e.x, 2 * p);
        int vB = __shfl_sync(0xffffffffu, e.x, 2 * p + 1);
        redadd(acc + (size_t)vA * 32 + lane, rA);
        redadd(acc + (size_t)vB * 32 + lane, rB);
    }
}

// ---------------------------------------------------------------------------
// epilogue with fused center tap:
//   conv = acc[v] + Wc0^T x0[v] (+ Wc1^T x1[v] for MODE 2)
//   MODE 0: y = relu(bn(conv))
//   MODE 1: y = relu(bn(conv) + res)
//   MODE 2: y = relu(bn(conv)) + xred(cat(x0,x1))
// ---------------------------------------------------------------------------
template <int MODE, typename T0, typename TOUT>
__global__ __launch_bounds__(256)
void epi(const float* __restrict__ acc, const float* __restrict__ bnp,
         const T0* __restrict__ x0, const float* __restrict__ Wc0,
         const __half* __restrict__ x1, const float* __restrict__ Wc1,
         const float* __restrict__ res,
         TOUT* __restrict__ out, int n)
{
    __shared__ u64 ft[8 * 512];
    const int lane = threadIdx.x & 31;
    const int warp = threadIdx.x >> 5;
    const int base = (blockIdx.x * 8 + warp) * 32;
    if (base >= n) return;

    const float s = __ldg(bnp + lane) * rsqrtf(__ldg(bnp + 96 + lane) + 1e-3f);
    const float b = __ldg(bnp + 32 + lane) - __ldg(bnp + 64 + lane) * s;

    u64* f = ft + warp * 512;
    // stage x0 rows (center-tap input)
    #pragma unroll 4
    for (int p = 0; p < 16; ++p) {
        int uA = base + 2 * p;     if (uA >= n) uA = 0;
        int uB = base + 2 * p + 1; if (uB >= n) uB = 0;
        f[p * 32 + lane] = pack2(loadf(x0 + (size_t)uA * 32 + lane),
                                 loadf(x0 + (size_t)uB * 32 + lane));
    }
    __syncwarp();

    if (MODE != 2) {
        u64 wsp[32];
        #pragma unroll
        for (int c = 0; c < 32; ++c) wsp[c] = splat2(__ldg(Wc0 + c * 32 + lane));

        #pragma unroll 2
        for (int p = 0; p < 16; ++p) {
            float rA, rB;
            pair_gemm(f, wsp, p, rA, rB);
            int vA = base + 2 * p, vB = vA + 1;
            int uA = (vA < n) ? vA : 0;
            int uB = (vB < n) ? vB : 0;
            float yA = (acc[(size_t)uA * 32 + lane] + rA) * s + b;
            float yB = (acc[(size_t)uB * 32 + lane] + rB) * s + b;
            if (MODE == 1) {
                yA += __ldg(res + (size_t)uA * 32 + lane);
                yB += __ldg(res + (size_t)uB * 32 + lane);
            }
            yA = fmaxf(yA, 0.0f);
            yB = fmaxf(yB, 0.0f);
            if (vA < n) storef(out + (size_t)vA * 32 + lane, yA);
            if (vB < n) storef(out + (size_t)vB * 32 + lane, yB);
        }
    } else {
        float rr[32];
        {
            u64 wsp[32];
            #pragma unroll
            for (int c = 0; c < 32; ++c) wsp[c] = splat2(__ldg(Wc0 + c * 32 + lane));
            #pragma unroll 2
            for (int p = 0; p < 16; ++p) pair_gemm(f, wsp, p, rr[2 * p], rr[2 * p + 1]);
        }
        __syncwarp();
        // restage x1 (second cat half, fp16)
        #pragma unroll 4
        for (int p = 0; p < 16; ++p) {
            int uA = base + 2 * p;     if (uA >= n) uA = 0;
            int uB = base + 2 * p + 1; if (uB >= n) uB = 0;
            f[p * 32 + lane] = pack2(loadf(x1 + (size_t)uA * 32 + lane),
                                     loadf(x1 + (size_t)uB * 32 + lane));
        }
        __syncwarp();
        {
            u64 wsp[32];
            #pragma unroll
            for (int c = 0; c < 32; ++c) wsp[c] = splat2(__ldg(Wc1 + c * 32 + lane));
            #pragma unroll 2
            for (int p = 0; p < 16; ++p) {
                float tA, tB;
                pair_gemm(f, wsp, p, tA, tB);
                rr[2 * p] += tA;
                rr[2 * p + 1] += tB;
            }
        }

        #pragma unroll 2
        for (int p = 0; p < 16; ++p) {
            int vA = base + 2 * p, vB = vA + 1;
            int uA = (vA < n) ? vA : 0;
            int uB = (vB < n) ? vB : 0;
            float yA = (acc[(size_t)uA * 32 + lane] + rr[2 * p])     * s + b;
            float yB = (acc[(size_t)uB * 32 + lane] + rr[2 * p + 1]) * s + b;
            yA = fmaxf(yA, 0.0f);
            yB = fmaxf(yB, 0.0f);
            // xred of cat(x0, x1): lane<16 from x0 (fp32), lane>=16 from x1 (fp16)
            if (lane < 16) {
                float2 tA = __ldg((const float2*)((const float*)x0 + (size_t)uA * 32 + 2 * lane));
                float2 tB = __ldg((const float2*)((const float*)x0 + (size_t)uB * 32 + 2 * lane));
                yA += tA.x + tA.y;
                yB += tB.x + tB.y;
            } else {
                float2 tA = __half22float2(__ldg((const __half2*)(x1 + (size_t)uA * 32 + 2 * (lane - 16))));
                float2 tB = __half22float2(__ldg((const __half2*)(x1 + (size_t)uB * 32 + 2 * (lane - 16))));
                yA += tA.x + tA.y;
                yB += tB.x + tB.y;
            }
            if (vA < n) storef(out + (size_t)vA * 32 + lane, yA);
            if (vB < n) storef(out + (size_t)vB * 32 + lane, yB);
        }
    }
}

// ---------------------------------------------------------------------------
extern "C" void kernel_launch(void* const* d_in, const int* in_sizes, int n_in,
                              void* d_out, int out_size)
{
    const float* lat  = (const float*)d_in[0];
    const float* bot  = (const float*)d_in[1];
    const float* Wt1  = (const float*)d_in[2];
    const float* bnt1 = (const float*)d_in[3];
    const float* Wt2  = (const float*)d_in[4];
    const float* bnt2 = (const float*)d_in[5];
    const float* Wm   = (const float*)d_in[6];
    const float* bnm  = (const float*)d_in[7];
    const float* Wi   = (const float*)d_in[8];
    const float* bni  = (const float*)d_in[9];
    const int*   nbr  = (const int*)d_in[10];

    const int n = in_sizes[0] / NC;

    float* accb;
    __half *h1, *h2, *h3;
    int* kcnt;
    cudaGetSymbolAddress((void**)&accb, g_acc);
    cudaGetSymbolAddress((void**)&h1, g_h1);
    cudaGetSymbolAddress((void**)&h2, g_h2);
    cudaGetSymbolAddress((void**)&h3, g_h3);
    cudaGetSymbolAddress((void**)&kcnt, g_kcnt);

    float* a1 = accb;
    float* a2 = accb + 1 * ASTRIDE;
    float* a3 = accb + 2 * ASTRIDE;
    float* a4 = accb + 3 * ASTRIDE;

    static cudaStream_t s1 = nullptr, s2 = nullptr;
    static cudaEvent_t e0 = nullptr, e1 = nullptr, eB = nullptr, e2 = nullptr;
    if (!s1) {
        cudaStreamCreateWithFlags(&s1, cudaStreamNonBlocking);
        cudaStreamCreateWithFlags(&s2, cudaStreamNonBlocking);
        cudaEventCreateWithFlags(&e0, cudaEventDisableTiming);
        cudaEventCreateWithFlags(&e1, cudaEventDisableTiming);
        cudaEventCreateWithFlags(&eB, cudaEventDisableTiming);
        cudaEventCreateWithFlags(&e2, cudaEventDisableTiming);
    }

    const int gridC = (n + 255) / 256;
    const int gridN = NBK * BLKSEG;

    // fork: memset of all 4 acc slices (incl. pad rows) on s1, overlaps build_rb
    cudaMemsetAsync(kcnt, 0, 32 * sizeof(int), 0);
    cudaEventRecord(e0, 0);
    cudaStreamWaitEvent(s1, e0, 0);
    cudaMemsetAsync(accb, 0, 4 * ASTRIDE * sizeof(float), s1);
    cudaEventRecord(e1, s1);

    build_rb<<<gridC, 256>>>(nbr, n);
    cudaEventRecord(eB, 0);

    // fork: conv_m's bot-half neighbor pass runs concurrently with conv1/conv2
    cudaStreamWaitEvent(s2, eB, 0);
    cudaStreamWaitEvent(s2, e1, 0);
    nb_conv<float><<<gridN, 256, 0, s2>>>(bot, Wm, 2048, 0, a3, n);
    cudaEventRecord(e2, s2);

    cudaStreamWaitEvent(0, e1, 0);

    // conv1: nb + (center fused in epi1) -> h1
    nb_conv<float><<<gridN, 256>>>(lat, Wt1, 1024, 0, a1, n);
    epi<0, float, __half><<<gridC, 256>>>(a1, bnt1, lat, Wt1 + 13 * 1024,
                                          nullptr, nullptr, nullptr, h1, n);

    // conv2: nb + epi2 (residual lat) -> h2
    nb_conv<__half><<<gridN, 256>>>(h1, Wt2, 1024, 0, a2, n);
    epi<1, __half, __half><<<gridC, 256>>>(a2, bnt2, h1, Wt2 + 13 * 1024,
                                           nullptr, nullptr, lat, h2, n);

    // conv_m: h2-half nb; join bot-half; epi3 (2-half center + xred) -> h3
    nb_conv<__half><<<gridN, 256>>>(h2, Wm, 2048, 1024, a3, n);
    cudaStreamWaitEvent(0, e2, 0);
    epi<2, float, __half><<<gridC, 256>>>(a3, bnm, bot, Wm + 13 * 2048,
                                          h2, Wm + 13 * 2048 + 1024, nullptr, h3, n);

    // conv_inv: nb + epi4 -> out (fp32)
    nb_conv<__half><<<gridN, 256>>>(h3, Wi, 1024, 0, a4, n);
    epi<0, __half, float><<<gridC, 256>>>(a4, bni, h3, Wi + 13 * 1024,
                                          nullptr, nullptr, nullptr, (float*)d_out, n);
}

// round 8
// speedup vs baseline: 1.0783x; 1.0783x over previous
#include <cuda_runtime.h>
#include <cuda_fp16.h>

// ---------------------------------------------------------------------------
// UNetV2 on GB300: gather-GEMM-scatter subm conv.
//  - fp16x2 atomic neighbor accumulators (halved acc traffic + atomics)
//  - center tap fused into epilogue (fp32), per-slice memsets on side stream
//  - bot-half nb conv forked onto side stream, overlapping conv1/conv2
// ---------------------------------------------------------------------------

#define MAXN 500000
#define NC   32
#define SEG  16384
#define NBK  26
#define BLKSEG 64
#define ASTRIDE ((size_t)(MAXN + 1) * NC)       // halves per acc slice (pad row at n)
#define ACCBYTES (ASTRIDE * sizeof(__half))

static __device__ __half g_acc[4 * ASTRIDE];
static __device__ __half g_h1[MAXN * NC];
static __device__ __half g_h2[MAXN * NC];
static __device__ __half g_h3[MAXN * NC];
static __device__ int2   g_rb[NBK * SEG];
static __device__ int    g_kcnt[32];

typedef unsigned long long u64;

__device__ __forceinline__ u64 splat2(float a) {
    u64 r; asm("mov.b64 %0, {%1, %1};" : "=l"(r) : "f"(a)); return r;
}
__device__ __forceinline__ u64 pack2(float a, float b) {
    u64 r; asm("mov.b64 %0, {%1, %2};" : "=l"(r) : "f"(a), "f"(b)); return r;
}
__device__ __forceinline__ void fma2(u64& d, u64 a, u64 b) {
    asm("fma.rn.f32x2 %0, %1, %2, %3;" : "=l"(d) : "l"(a), "l"(b), "l"(d));
}
__device__ __forceinline__ float2 unpack2(u64 a) {
    float2 r; asm("mov.b64 {%0, %1}, %2;" : "=f"(r.x), "=f"(r.y) : "l"(a)); return r;
}
// pack two fp32 -> f16x2 (lo = first arg, hi = second arg)
__device__ __forceinline__ unsigned cvt_h2(float lo, float hi) {
    unsigned r;
    asm("cvt.rn.f16x2.f32 %0, %1, %2;" : "=r"(r) : "f"(hi), "f"(lo));
    return r;
}
__device__ __forceinline__ void redadd_h2(__half* p, unsigned hv) {
    asm volatile("red.global.add.noftz.f16x2 [%0], %1;" :: "l"(p), "r"(hv) : "memory");
}
__device__ __forceinline__ float loadf(const float* p)  { return __ldg(p); }
__device__ __forceinline__ float loadf(const __half* p) { return __half2float(__ldg(p)); }
__device__ __forceinline__ void storef(float* p, float v)  { *p = v; }
__device__ __forceinline__ void storef(__half* p, float v) { *p = __float2half(v); }

// ---------------------------------------------------------------------------
__global__ __launch_bounds__(256)
void build_rb(const int* __restrict__ nbr, int n)
{
    __shared__ int nsh[256 * 27];
    const int tid  = threadIdx.x;
    const int lane = tid & 31;
    const long long base = (long long)blockIdx.x * 256;

    for (int i = tid; i < 256 * 27; i += 256) {
        long long g = base * 27 + i;
        nsh[i] = (g < (long long)n * 27) ? nbr[g] : n;
    }
    __syncthreads();

    const int v = (int)(base + tid);
    const bool live = v < n;

    #pragma unroll 1
    for (int j = 0; j < NBK; ++j) {
        int k = (j < 13) ? j : j + 1;
        int u = nsh[tid * 27 + k];
        bool want = live && ((unsigned)u < (unsigned)n);
        unsigned m = __ballot_sync(0xffffffffu, want);
        int rank = __popc(m & ((1u << lane) - 1));
        int leader = (m != 0u) ? (__ffs(m) - 1) : 0;
        int bp = 0;
        if (m != 0u && lane == leader) bp = atomicAdd(&g_kcnt[j], __popc(m));
        bp = __shfl_sync(0xffffffffu, bp, leader);
        int pos = bp + rank;
        if (want && pos < SEG) g_rb[j * SEG + pos] = make_int2(v, u);
    }
}

// ---------------------------------------------------------------------------
__device__ __forceinline__ void pair_gemm(const u64* f, const u64* wsp, int p,
                                          float& rA, float& rB)
{
    const ulonglong2* row = (const ulonglong2*)(f + p * 32);
    u64 aE = 0ull, aO = 0ull;
    #pragma unroll
    for (int c2 = 0; c2 < 16; ++c2) {
        ulonglong2 q = row[c2];
        fma2(aE, q.x, wsp[2 * c2]);
        fma2(aO, q.y, wsp[2 * c2 + 1]);
    }
    float2 e = unpack2(aE), o = unpack2(aO);
    rA = e.x + o.x;
    rB = e.y + o.y;
}

// ---------------------------------------------------------------------------
// neighbor taps: acc[v] += Wk^T x[u] (fp16x2 atomics, pad row at v==n)
// ---------------------------------------------------------------------------
template <typename T>
__global__ __launch_bounds__(256)
void nb_conv(const T* __restrict__ x, const float* __restrict__ W,
             int kstride, int hoff, __half* __restrict__ acc, int n)
{
    __shared__ u64 ft[8 * 512];
    const int j   = blockIdx.x / BLKSEG;
    const int bis = blockIdx.x % BLKSEG;
    const int cnt = g_kcnt[j];
    if (bis * 256 >= cnt) return;

    const int k = (j < 13) ? j : j + 1;
    const float* Wk = W + (size_t)k * kstride + hoff;

    const int lane = threadIdx.x & 31;
    const int warp = threadIdx.x >> 5;

    u64 wsp[32];
    #pragma unroll
    for (int c = 0; c < 32; ++c) wsp[c] = splat2(__ldg(Wk + c * 32 + lane));

    const int eidx = bis * 256 + warp * 32 + lane;
    int2 e = (eidx < cnt) ? __ldg(&g_rb[j * SEG + eidx]) : make_int2(n, 0);

    u64* f = ft + warp * 512;
    #pragma unroll 4
    for (int p = 0; p < 16; ++p) {
        int uA = __shfl_sync(0xffffffffu, e.y, 2 * p);
        int uB = __shfl_sync(0xffffffffu, e.y, 2 * p + 1);
        f[p * 32 + lane] = pack2(loadf(x + (size_t)uA * 32 + lane),
                                 loadf(x + (size_t)uB * 32 + lane));
    }
    __syncwarp();

    #pragma unroll 2
    for (int p = 0; p < 16; ++p) {
        float rA, rB;
        pair_gemm(f, wsp, p, rA, rB);
        int vA = __shfl_sync(0xffffffffu, e.x, 2 * p);
        int vB = __shfl_sync(0xffffffffu, e.x, 2 * p + 1);
        // pair adjacent couts: even lanes own entry A, odd lanes entry B
        float pA = __shfl_xor_sync(0xffffffffu, rA, 1);
        float pB = __shfl_xor_sync(0xffffffffu, rB, 1);
        unsigned hv;
        int v;
        if ((lane & 1) == 0) { hv = cvt_h2(rA, pA); v = vA; }   // (cout L, L+1) of A
        else                 { hv = cvt_h2(pB, rB); v = vB; }   // (cout L-1, L) of B
        redadd_h2(acc + (size_t)v * 32 + (lane & ~1), hv);
    }
}

// ---------------------------------------------------------------------------
// epilogue with fused center tap:
//   conv = acc[v] + Wc0^T x0[v] (+ Wc1^T x1[v] for MODE 2)
//   MODE 0: y = relu(bn(conv))
//   MODE 1: y = relu(bn(conv) + res)
//   MODE 2: y = relu(bn(conv)) + xred(cat(x0,x1))
// ---------------------------------------------------------------------------
template <int MODE, typename T0, typename TOUT>
__global__ __launch_bounds__(256, 4)
void epi(const __half* __restrict__ acc, const float* __restrict__ bnp,
         const T0* __restrict__ x0, const float* __restrict__ Wc0,
         const __half* __restrict__ x1, const float* __restrict__ Wc1,
         const float* __restrict__ res,
         TOUT* __restrict__ out, int n)
{
    __shared__ u64 ft[8 * 512];
    const int lane = threadIdx.x & 31;
    const int warp = threadIdx.x >> 5;
    const int base = (blockIdx.x * 8 + warp) * 32;
    if (base >= n) return;

    const float s = __ldg(bnp + lane) * rsqrtf(__ldg(bnp + 96 + lane) + 1e-3f);
    const float b = __ldg(bnp + 32 + lane) - __ldg(bnp + 64 + lane) * s;

    u64* f = ft + warp * 512;
    // stage x0 rows (center-tap input)
    #pragma unroll 4
    for (int p = 0; p < 16; ++p) {
        int uA = base + 2 * p;     if (uA >= n) uA = 0;
        int uB = base + 2 * p + 1; if (uB >= n) uB = 0;
        f[p * 32 + lane] = pack2(loadf(x0 + (size_t)uA * 32 + lane),
                                 loadf(x0 + (size_t)uB * 32 + lane));
    }
    __syncwarp();

    if (MODE != 2) {
        u64 wsp[32];
        #pragma unroll
        for (int c = 0; c < 32; ++c) wsp[c] = splat2(__ldg(Wc0 + c * 32 + lane));

        #pragma unroll 2
        for (int p = 0; p < 16; ++p) {
            float rA, rB;
            pair_gemm(f, wsp, p, rA, rB);
            int vA = base + 2 * p, vB = vA + 1;
            int uA = (vA < n) ? vA : 0;
            int uB = (vB < n) ? vB : 0;
            float yA = (loadf(acc + (size_t)uA * 32 + lane) + rA) * s + b;
            float yB = (loadf(acc + (size_t)uB * 32 + lane) + rB) * s + b;
            if (MODE == 1) {
                yA += __ldg(res + (size_t)uA * 32 + lane);
                yB += __ldg(res + (size_t)uB * 32 + lane);
            }
            yA = fmaxf(yA, 0.0f);
            yB = fmaxf(yB, 0.0f);
            if (vA < n) storef(out + (size_t)vA * 32 + lane, yA);
            if (vB < n) storef(out + (size_t)vB * 32 + lane, yB);
        }
    } else {
        float rr[32];
        {
            u64 wsp[32];
            #pragma unroll
            for (int c = 0; c < 32; ++c) wsp[c] = splat2(__ldg(Wc0 + c * 32 + lane));
            #pragma unroll 2
            for (int p = 0; p < 16; ++p) pair_gemm(f, wsp, p, rr[2 * p], rr[2 * p + 1]);
        }
        __syncwarp();
        // restage x1 (second cat half, fp16)
        #pragma unroll 4
        for (int p = 0; p < 16; ++p) {
            int uA = base + 2 * p;     if (uA >= n) uA = 0;
            int uB = base + 2 * p + 1; if (uB >= n) uB = 0;
            f[p * 32 + lane] = pack2(loadf(x1 + (size_t)uA * 32 + lane),
                                     loadf(x1 + (size_t)uB * 32 + lane));
        }
        __syncwarp();
        {
            u64 wsp[32];
            #pragma unroll
            for (int c = 0; c < 32; ++c) wsp[c] = splat2(__ldg(Wc1 + c * 32 + lane));
            #pragma unroll 2
            for (int p = 0; p < 16; ++p) {
                float tA, tB;
                pair_gemm(f, wsp, p, tA, tB);
                rr[2 * p] += tA;
                rr[2 * p + 1] += tB;
            }
        }

        #pragma unroll 2
        for (int p = 0; p < 16; ++p) {
            int vA = base + 2 * p, vB = vA + 1;
            int uA = (vA < n) ? vA : 0;
            int uB = (vB < n) ? vB : 0;
            float yA = (loadf(acc + (size_t)uA * 32 + lane) + rr[2 * p])     * s + b;
            float yB = (loadf(acc + (size_t)uB * 32 + lane) + rr[2 * p + 1]) * s + b;
            yA = fmaxf(yA, 0.0f);
            yB = fmaxf(yB, 0.0f);
            if (lane < 16) {
                float2 tA = __ldg((const float2*)((const float*)x0 + (size_t)uA * 32 + 2 * lane));
                float2 tB = __ldg((const float2*)((const float*)x0 + (size_t)uB * 32 + 2 * lane));
                yA += tA.x + tA.y;
                yB += tB.x + tB.y;
            } else {
                float2 tA = __half22float2(__ldg((const __half2*)(x1 + (size_t)uA * 32 + 2 * (lane - 16))));
                float2 tB = __half22float2(__ldg((const __half2*)(x1 + (size_t)uB * 32 + 2 * (lane - 16))));
                yA += tA.x + tA.y;
                yB += tB.x + tB.y;
            }
            if (vA < n) storef(out + (size_t)vA * 32 + lane, yA);
            if (vB < n) storef(out + (size_t)vB * 32 + lane, yB);
        }
    }
}

// ---------------------------------------------------------------------------
extern "C" void kernel_launch(void* const* d_in, const int* in_sizes, int n_in,
                              void* d_out, int out_size)
{
    const float* lat  = (const float*)d_in[0];
    const float* bot  = (const float*)d_in[1];
    const float* Wt1  = (const float*)d_in[2];
    const float* bnt1 = (const float*)d_in[3];
    const float* Wt2  = (const float*)d_in[4];
    const float* bnt2 = (const float*)d_in[5];
    const float* Wm   = (const float*)d_in[6];
    const float* bnm  = (const float*)d_in[7];
    const float* Wi   = (const float*)d_in[8];
    const float* bni  = (const float*)d_in[9];
    const int*   nbr  = (const int*)d_in[10];

    const int n = in_sizes[0] / NC;

    __half *accb, *h1, *h2, *h3;
    int* kcnt;
    cudaGetSymbolAddress((void**)&accb, g_acc);
    cudaGetSymbolAddress((void**)&h1, g_h1);
    cudaGetSymbolAddress((void**)&h2, g_h2);
    cudaGetSymbolAddress((void**)&h3, g_h3);
    cudaGetSymbolAddress((void**)&kcnt, g_kcnt);

    __half* a1 = accb;
    __half* a2 = accb + 1 * ASTRIDE;
    __half* a3 = accb + 2 * ASTRIDE;
    __half* a4 = accb + 3 * ASTRIDE;

    static cudaStream_t s1 = nullptr, s2 = nullptr;
    static cudaEvent_t e0 = nullptr, eB = nullptr, e2 = nullptr;
    static cudaEvent_t em1 = nullptr, em2 = nullptr, em3 = nullptr, em4 = nullptr;
    if (!s1) {
        cudaStreamCreateWithFlags(&s1, cudaStreamNonBlocking);
        cudaStreamCreateWithFlags(&s2, cudaStreamNonBlocking);
        cudaEventCreateWithFlags(&e0, cudaEventDisableTiming);
        cudaEventCreateWithFlags(&eB, cudaEventDisableTiming);
        cudaEventCreateWithFlags(&e2, cudaEventDisableTiming);
        cudaEventCreateWithFlags(&em1, cudaEventDisableTiming);
        cudaEventCreateWithFlags(&em2, cudaEventDisableTiming);
        cudaEventCreateWithFlags(&em3, cudaEventDisableTiming);
        cudaEventCreateWithFlags(&em4, cudaEventDisableTiming);
    }

    const int gridC = (n + 255) / 256;
    const int gridN = NBK * BLKSEG;

    // fork: per-slice memsets on s1 (a1 first so nb1 is never gated)
    cudaMemsetAsync(kcnt, 0, 32 * sizeof(int), 0);
    cudaEventRecord(e0, 0);
    cudaStreamWaitEvent(s1, e0, 0);
    cudaMemsetAsync(a1, 0, ACCBYTES, s1); cudaEventRecord(em1, s1);
    cudaMemsetAsync(a3, 0, ACCBYTES, s1); cudaEventRecord(em3, s1);
    cudaMemsetAsync(a2, 0, ACCBYTES, s1); cudaEventRecord(em2, s1);
    cudaMemsetAsync(a4, 0, ACCBYTES, s1); cudaEventRecord(em4, s1);

    build_rb<<<gridC, 256>>>(nbr, n);
    cudaEventRecord(eB, 0);

    // fork: conv_m's bot-half neighbor pass overlaps conv1/conv2
    cudaStreamWaitEvent(s2, eB, 0);
    cudaStreamWaitEvent(s2, em3, 0);
    nb_conv<float><<<gridN, 256, 0, s2>>>(bot, Wm, 2048, 0, a3, n);
    cudaEventRecord(e2, s2);

    // conv1
    cudaStreamWaitEvent(0, em1, 0);
    nb_conv<float><<<gridN, 256>>>(lat, Wt1, 1024, 0, a1, n);
    epi<0, float, __half><<<gridC, 256>>>(a1, bnt1, lat, Wt1 + 13 * 1024,
                                          nullptr, nullptr, nullptr, h1, n);

    // conv2
    cudaStreamWaitEvent(0, em2, 0);
    nb_conv<__half><<<gridN, 256>>>(h1, Wt2, 1024, 0, a2, n);
    epi<1, __half, __half><<<gridC, 256>>>(a2, bnt2, h1, Wt2 + 13 * 1024,
                                           nullptr, nullptr, lat, h2, n);

    // conv_m
    nb_conv<__half><<<gridN, 256>>>(h2, Wm, 2048, 1024, a3, n);
    cudaStreamWaitEvent(0, e2, 0);
    epi<2, float, __half><<<gridC, 256>>>(a3, bnm, bot, Wm + 13 * 2048,
                                          h2, Wm + 13 * 2048 + 1024, nullptr, h3, n);

    // conv_inv
    cudaStreamWaitEvent(0, em4, 0);
    nb_conv<__half><<<gridN, 256>>>(h3, Wi, 1024, 0, a4, n);
    epi<0, __half, float><<<gridC, 256>>>(a4, bni, h3, Wi + 13 * 1024,
                                          nullptr, nullptr, nullptr, (float*)d_out, n);
}